// round 1
// baseline (speedup 1.0000x reference)
#include <cuda_runtime.h>
#include <stdint.h>

// Problem constants (from reference)
#define NSYM  128
#define DW    32     // D_WORLDS
#define K2D   64     // 2*D_WORLDS (concat of l and r)
#define NW    512    // N_WORLDS
#define BATCH 2048

// Packed dual-fp32 FMA (Blackwell sm_100+ PTX-only instruction)
#define FMA2(dst, a, b, c) \
    asm("fma.rn.f32x2 %0, %1, %2, %3;" : "=l"(dst) : "l"(a), "l"(b), "l"(c))

__global__ __launch_bounds__(256, 2)
void binop_fused_kernel(const float* __restrict__ states,   // [8*2048, 32, 512]
                        const float* __restrict__ W,        // [128, 32, 64]
                        const float* __restrict__ b,        // [128, 32]
                        const int*   __restrict__ indices,  // [2048]
                        const int*   __restrict__ symbols,  // [2048]
                        const int*   __restrict__ args,     // [2048, 2]
                        float*       __restrict__ out)      // [2048, 32, 512]
{
    // Duplicated W tile: ws2[d*64 + k] = {W[sym][d][k], W[sym][d][k]}
    __shared__ __align__(16) float2 ws2[DW * K2D];
    __shared__ float bsh[DW];

    const int n = blockIdx.x;
    const int t = threadIdx.x;   // owns world columns (2t, 2t+1)

    const int idx = indices[n];
    const int sym = symbols[n];
    const int a0  = args[2 * n];
    const int a1  = args[2 * n + 1];

    // Load + duplicate W[sym] into smem
    const float* Wp = W + (size_t)sym * (DW * K2D);
    #pragma unroll
    for (int i = t; i < DW * K2D; i += 256) {
        float v = Wp[i];
        ws2[i] = make_float2(v, v);
    }
    if (t < DW) bsh[t] = b[sym * DW + t];
    __syncthreads();

    // l/r state rows; each thread reads the 64-bit pair at column 2t
    const uint64_t* lp = (const uint64_t*)(states + (size_t)(a0 * BATCH + idx) * (DW * NW)) + t;
    const uint64_t* rp = (const uint64_t*)(states + (size_t)(a1 * BATCH + idx) * (DW * NW)) + t;

    // Packed accumulators: acc[d] = {y[d][2t], y[d][2t+1]}, init to bias
    uint64_t acc[DW];
    #pragma unroll
    for (int d = 0; d < DW; d++) {
        float bv = bsh[d];
        asm("mov.b64 %0, {%1,%2};" : "=l"(acc[d]) : "f"(bv), "f"(bv));
    }

    #pragma unroll 1
    for (int half = 0; half < 2; half++) {
        const uint64_t* xp = half ? rp : lp;
        const int kbase = half * 32;

        uint64_t x0 = xp[0];
        uint64_t x1 = xp[256];          // row stride = 512 floats = 256 u64

        #pragma unroll 1
        for (int kp = 0; kp < 16; kp++) {
            // Prefetch next k-pair (clamped at the tail; values unused then)
            const int kn = (2 * kp + 2 < 32) ? (2 * kp + 2) : 30;
            uint64_t nx0 = xp[(size_t)kn * 256];
            uint64_t nx1 = xp[(size_t)(kn + 1) * 256];

            const int k = kbase + 2 * kp;
            #pragma unroll
            for (int d = 0; d < DW; d++) {
                // One LDS.128 fetches ws2[d][k] and ws2[d][k+1] (broadcast)
                ulonglong2 wv = *reinterpret_cast<const ulonglong2*>(&ws2[d * K2D + k]);
                FMA2(acc[d], wv.x, x0, acc[d]);
                FMA2(acc[d], wv.y, x1, acc[d]);
            }
            x0 = nx0;
            x1 = nx1;
        }
    }

    // L2-normalize over d (thread-local, separately for each of the 2 columns)
    float sq_lo = 0.f, sq_hi = 0.f;
    #pragma unroll
    for (int d = 0; d < DW; d++) {
        float2 av = *reinterpret_cast<float2*>(&acc[d]);
        sq_lo = fmaf(av.x, av.x, sq_lo);
        sq_hi = fmaf(av.y, av.y, sq_hi);
    }
    const float s_lo = rsqrtf(fmaxf(sq_lo, 1e-12f));
    const float s_hi = rsqrtf(fmaxf(sq_hi, 1e-12f));

    // Scatter row = indices[n] (arange -> bijective, plain store covers all of out)
    uint64_t* op = (uint64_t*)(out + (size_t)idx * (DW * NW)) + t;
    #pragma unroll
    for (int d = 0; d < DW; d++) {
        float2 av = *reinterpret_cast<float2*>(&acc[d]);
        float2 r  = make_float2(av.x * s_lo, av.y * s_hi);
        op[(size_t)d * 256] = *reinterpret_cast<uint64_t*>(&r);
    }
}

extern "C" void kernel_launch(void* const* d_in, const int* in_sizes, int n_in,
                              void* d_out, int out_size) {
    const float* states  = (const float*)d_in[0];
    const float* W       = (const float*)d_in[1];
    const float* b       = (const float*)d_in[2];
    const int*   indices = (const int*)d_in[3];
    const int*   symbols = (const int*)d_in[4];
    const int*   args    = (const int*)d_in[5];
    float*       out     = (float*)d_out;

    binop_fused_kernel<<<BATCH, 256>>>(states, W, b, indices, symbols, args, out);
}